// round 10
// baseline (speedup 1.0000x reference)
#include <cuda_runtime.h>
#include <cuda_bf16.h>
#include <stdint.h>
#include <math.h>

// Problem dims
#define S_DIM 2048
#define E_DIM 2048
#define H_DIM 16
#define KD_DIM 128
#define FF_DIM 8192
#define EPS 1e-5f
#define NTOT (2048L * 2048L)

// ---------------- scratch (device globals; no allocations allowed) ----------
__device__ float  g_q [(long)H_DIM * S_DIM * KD_DIM];
__device__ float  g_k [(long)H_DIM * S_DIM * KD_DIM];
__device__ float  g_v [(long)H_DIM * S_DIM * E_DIM];
__device__ float  g_sc[(long)H_DIM * S_DIM * S_DIM];
__device__ float  g_y [(long)S_DIM * E_DIM];
__device__ float  g_h [(long)S_DIM * E_DIM];
__device__ float  g_ff[(long)S_DIM * FF_DIM];
__device__ double g_part[2048];
__device__ float  g_stats[2];

// =====================  bf16-split tensor-core GEMM engine  =================
// Block tile 128x128, BK=16, 128 threads = 4 warps in 2x2, warp tile 64x64
// -> 4(M) x 8(N) mma atoms per warp, 96 HMMA per warp per k16 stage.
// A = Ah + Al, B = Bh + Bl (bf16 each); acc += AhBh + AhBl + AlBh.
// Double-buffered smem stages: one __syncthreads per stage.
// PITCH 136: bank = (8*k2row + g) % 32 -> conflict-free fragment loads.
#define PITCH 136

struct SmemTiles {
    uint32_t AsH[8][PITCH];
    uint32_t AsL[8][PITCH];
    uint32_t BsH[8][PITCH];
    uint32_t BsL[8][PITCH];
};

__device__ __forceinline__ void split_pair(float f0, float f1,
                                           uint32_t &hi, uint32_t &lo)
{
    __nv_bfloat16 h0 = __float2bfloat16_rn(f0);
    __nv_bfloat16 h1 = __float2bfloat16_rn(f1);
    __nv_bfloat16 l0 = __float2bfloat16_rn(f0 - __bfloat162float(h0));
    __nv_bfloat16 l1 = __float2bfloat16_rn(f1 - __bfloat162float(h1));
    unsigned short u0 = __bfloat16_as_ushort(h0);
    unsigned short u1 = __bfloat16_as_ushort(h1);
    unsigned short w0 = __bfloat16_as_ushort(l0);
    unsigned short w1 = __bfloat16_as_ushort(l1);
    hi = (uint32_t)u0 | ((uint32_t)u1 << 16);
    lo = (uint32_t)w0 | ((uint32_t)w1 << 16);
}

__device__ __forceinline__ void mma16816(float *c, const uint32_t *a,
                                         const uint32_t *b)
{
    asm volatile(
        "mma.sync.aligned.m16n8k16.row.col.f32.bf16.bf16.f32 "
        "{%0,%1,%2,%3},{%4,%5,%6,%7},{%8,%9},{%0,%1,%2,%3};\n"
        : "+f"(c[0]), "+f"(c[1]), "+f"(c[2]), "+f"(c[3])
        : "r"(a[0]), "r"(a[1]), "r"(a[2]), "r"(a[3]), "r"(b[0]), "r"(b[1]));
}

// one k16 step for a 64x64 warp tile (4 M-atoms x 8 N-atoms)
__device__ __forceinline__ void compute_stage(const SmemTiles *sm,
    float acc[4][8][4], int m0w, int n0w, int g, int t)
{
    uint32_t bh[8][2];
    uint32_t bl[8][2];
    int na, ma;
    #pragma unroll
    for (na = 0; na < 8; na++) {
        int c = n0w + na * 8 + g;
        bh[na][0] = sm->BsH[t][c];
        bh[na][1] = sm->BsH[t + 4][c];
        bl[na][0] = sm->BsL[t][c];
        bl[na][1] = sm->BsL[t + 4][c];
    }
    #pragma unroll
    for (ma = 0; ma < 4; ma++) {
        int r0 = m0w + ma * 16 + g;
        uint32_t ah[4];
        uint32_t al[4];
        ah[0] = sm->AsH[t][r0];
        ah[1] = sm->AsH[t][r0 + 8];
        ah[2] = sm->AsH[t + 4][r0];
        ah[3] = sm->AsH[t + 4][r0 + 8];
        al[0] = sm->AsL[t][r0];
        al[1] = sm->AsL[t][r0 + 8];
        al[2] = sm->AsL[t + 4][r0];
        al[3] = sm->AsL[t + 4][r0 + 8];
        #pragma unroll
        for (na = 0; na < 8; na++) {
            mma16816(acc[ma][na], ah, bh[na]);
            mma16816(acc[ma][na], ah, bl[na]);
            mma16816(acc[ma][na], al, bh[na]);
        }
    }
}

// stage one full row of a row-major [128 x 16] tile (thread owns row = tid):
// 16 consecutive k floats -> smem rows 0..7 (k-pairs), column = row.
__device__ __forceinline__ void store_colstage16(uint32_t (*Hi)[PITCH],
    uint32_t (*Lo)[PITCH], float4 v0, float4 v1, float4 v2, float4 v3, int row)
{
    split_pair(v0.x, v0.y, Hi[0][row], Lo[0][row]);
    split_pair(v0.z, v0.w, Hi[1][row], Lo[1][row]);
    split_pair(v1.x, v1.y, Hi[2][row], Lo[2][row]);
    split_pair(v1.z, v1.w, Hi[3][row], Lo[3][row]);
    split_pair(v2.x, v2.y, Hi[4][row], Lo[4][row]);
    split_pair(v2.z, v2.w, Hi[5][row], Lo[5][row]);
    split_pair(v3.x, v3.y, Hi[6][row], Lo[6][row]);
    split_pair(v3.z, v3.w, Hi[7][row], Lo[7][row]);
}

// stage a row-major [16 x 128] B tile chunk: thread owns k2 = tid>>4,
// cols (tid&15)*8 .. +7; r00/r01 from k-row 2*k2, r10/r11 from k-row 2*k2+1.
__device__ __forceinline__ void store_rowstage8(SmemTiles *sm,
    float4 r00, float4 r01, float4 r10, float4 r11, int k2, int nc)
{
    split_pair(r00.x, r10.x, sm->BsH[k2][nc + 0], sm->BsL[k2][nc + 0]);
    split_pair(r00.y, r10.y, sm->BsH[k2][nc + 1], sm->BsL[k2][nc + 1]);
    split_pair(r00.z, r10.z, sm->BsH[k2][nc + 2], sm->BsL[k2][nc + 2]);
    split_pair(r00.w, r10.w, sm->BsH[k2][nc + 3], sm->BsL[k2][nc + 3]);
    split_pair(r01.x, r11.x, sm->BsH[k2][nc + 4], sm->BsL[k2][nc + 4]);
    split_pair(r01.y, r11.y, sm->BsH[k2][nc + 5], sm->BsL[k2][nc + 5]);
    split_pair(r01.z, r11.z, sm->BsH[k2][nc + 6], sm->BsL[k2][nc + 6]);
    split_pair(r01.w, r11.w, sm->BsH[k2][nc + 7], sm->BsL[k2][nc + 7]);
}

// ---------------- C = A[M,K] @ B[K,N] (+bias)(+resid)(relu), batched z ------
__global__ void __launch_bounds__(128) mma_gemm_nn(
    const float *Ag, const float *Bg,
    const float *bias, const float *resid,
    float *Cg, int K, int N,
    long sB, long sBias, long sC, int relu)
{
    __shared__ SmemTiles sm[2];

    const float *A = Ag;
    const float *B = Bg + (long)blockIdx.z * sB;
    const float *bi = (bias != 0) ? (bias + (long)blockIdx.z * sBias) : (const float *)0;
    float *C = Cg + (long)blockIdx.z * sC;

    int tid = threadIdx.x;
    int lane = tid & 31;
    int warp = tid >> 5;
    int g = lane >> 2;
    int t = lane & 3;
    int m0w = (warp >> 1) * 64;
    int n0w = (warp & 1) * 64;
    long row0 = (long)blockIdx.y * 128;
    long col0 = (long)blockIdx.x * 128;

    int bk2 = tid >> 4;          // 0..7
    int bnc = (tid & 15) * 8;    // 0..120

    float acc[4][8][4];
    int i0, i1, i2;
    #pragma unroll
    for (i0 = 0; i0 < 4; i0++)
        #pragma unroll
        for (i1 = 0; i1 < 8; i1++)
            #pragma unroll
            for (i2 = 0; i2 < 4; i2++)
                acc[i0][i1][i2] = 0.0f;

    const float *aptr = A + (row0 + tid) * (long)K;
    const float *bptr = B + col0 + bnc;
    long bstep0 = (long)(2 * bk2) * N;

    float4 pa0 = *(const float4 *)(aptr);
    float4 pa1 = *(const float4 *)(aptr + 4);
    float4 pa2 = *(const float4 *)(aptr + 8);
    float4 pa3 = *(const float4 *)(aptr + 12);
    float4 pb00 = *(const float4 *)(bptr + bstep0);
    float4 pb01 = *(const float4 *)(bptr + bstep0 + 4);
    float4 pb10 = *(const float4 *)(bptr + bstep0 + N);
    float4 pb11 = *(const float4 *)(bptr + bstep0 + N + 4);

    store_colstage16(sm[0].AsH, sm[0].AsL, pa0, pa1, pa2, pa3, tid);
    store_rowstage8(&sm[0], pb00, pb01, pb10, pb11, bk2, bnc);
    __syncthreads();

    int nsteps = K / 16;
    int s;
    for (s = 0; s < nsteps; s++) {
        int more = (s + 1 < nsteps) ? 1 : 0;
        if (more) {
            const float *ap2 = aptr + (s + 1) * 16;
            const float *bp2 = bptr + bstep0 + (long)(s + 1) * 16 * N;
            pa0 = *(const float4 *)(ap2);
            pa1 = *(const float4 *)(ap2 + 4);
            pa2 = *(const float4 *)(ap2 + 8);
            pa3 = *(const float4 *)(ap2 + 12);
            pb00 = *(const float4 *)(bp2);
            pb01 = *(const float4 *)(bp2 + 4);
            pb10 = *(const float4 *)(bp2 + N);
            pb11 = *(const float4 *)(bp2 + N + 4);
        }
        compute_stage(&sm[s & 1], acc, m0w, n0w, g, t);
        if (more) {
            store_colstage16(sm[(s + 1) & 1].AsH, sm[(s + 1) & 1].AsL,
                             pa0, pa1, pa2, pa3, tid);
            store_rowstage8(&sm[(s + 1) & 1], pb00, pb01, pb10, pb11, bk2, bnc);
            __syncthreads();
        }
    }

    int ma, na;
    #pragma unroll
    for (ma = 0; ma < 4; ma++) {
        long r = row0 + m0w + ma * 16 + g;
        #pragma unroll
        for (na = 0; na < 8; na++) {
            long c = col0 + n0w + na * 8 + 2 * t;
            float b0 = 0.0f;
            float b1 = 0.0f;
            if (bi != 0) {
                b0 = bi[c];
                b1 = bi[c + 1];
            }
            float v0 = acc[ma][na][0] + b0;
            float v1 = acc[ma][na][1] + b1;
            float w0 = acc[ma][na][2] + b0;
            float w1 = acc[ma][na][3] + b1;
            if (resid != 0) {
                v0 += resid[r * N + c];
                v1 += resid[r * N + c + 1];
                w0 += resid[(r + 8) * N + c];
                w1 += resid[(r + 8) * N + c + 1];
            }
            if (relu != 0) {
                v0 = fmaxf(v0, 0.0f);
                v1 = fmaxf(v1, 0.0f);
                w0 = fmaxf(w0, 0.0f);
                w1 = fmaxf(w1, 0.0f);
            }
            C[r * N + c]           = v0;
            C[r * N + c + 1]       = v1;
            C[(r + 8) * N + c]     = w0;
            C[(r + 8) * N + c + 1] = w1;
        }
    }
}

// ---------------- scores = (Q @ K^T)/sqrt(KD), causal block skip ------------
__global__ void __launch_bounds__(128) mma_gemm_nt_causal(
    const float *Qg, const float *Kg, float *SCg, float scale)
{
    __shared__ SmemTiles sm[2];

    if (blockIdx.x > blockIdx.y) return;
    const float *A = Qg + (long)blockIdx.z * S_DIM * KD_DIM;
    const float *B = Kg + (long)blockIdx.z * S_DIM * KD_DIM;
    float *C = SCg + (long)blockIdx.z * S_DIM * (long)S_DIM;

    int tid = threadIdx.x;
    int lane = tid & 31;
    int warp = tid >> 5;
    int g = lane >> 2;
    int t = lane & 3;
    int m0w = (warp >> 1) * 64;
    int n0w = (warp & 1) * 64;
    long row0 = (long)blockIdx.y * 128;
    long col0 = (long)blockIdx.x * 128;

    float acc[4][8][4];
    int i0, i1, i2;
    #pragma unroll
    for (i0 = 0; i0 < 4; i0++)
        #pragma unroll
        for (i1 = 0; i1 < 8; i1++)
            #pragma unroll
            for (i2 = 0; i2 < 4; i2++)
                acc[i0][i1][i2] = 0.0f;

    const float *aptr = A + (row0 + tid) * (long)KD_DIM;
    const float *bptr = B + (col0 + tid) * (long)KD_DIM;

    float4 pa0 = *(const float4 *)(aptr);
    float4 pa1 = *(const float4 *)(aptr + 4);
    float4 pa2 = *(const float4 *)(aptr + 8);
    float4 pa3 = *(const float4 *)(aptr + 12);
    float4 pb0 = *(const float4 *)(bptr);
    float4 pb1 = *(const float4 *)(bptr + 4);
    float4 pb2 = *(const float4 *)(bptr + 8);
    float4 pb3 = *(const float4 *)(bptr + 12);

    store_colstage16(sm[0].AsH, sm[0].AsL, pa0, pa1, pa2, pa3, tid);
    store_colstage16(sm[0].BsH, sm[0].BsL, pb0, pb1, pb2, pb3, tid);
    __syncthreads();

    int nsteps = KD_DIM / 16;
    int s;
    for (s = 0; s < nsteps; s++) {
        int more = (s + 1 < nsteps) ? 1 : 0;
        if (more) {
            const float *ap2 = aptr + (s + 1) * 16;
            const float *bp2 = bptr + (s + 1) * 16;
            pa0 = *(const float4 *)(ap2);
            pa1 = *(const float4 *)(ap2 + 4);
            pa2 = *(const float4 *)(ap2 + 8);
            pa3 = *(const float4 *)(ap2 + 12);
            pb0 = *(const float4 *)(bp2);
            pb1 = *(const float4 *)(bp2 + 4);
            pb2 = *(const float4 *)(bp2 + 8);
            pb3 = *(const float4 *)(bp2 + 12);
        }
        compute_stage(&sm[s & 1], acc, m0w, n0w, g, t);
        if (more) {
            store_colstage16(sm[(s + 1) & 1].AsH, sm[(s + 1) & 1].AsL,
                             pa0, pa1, pa2, pa3, tid);
            store_colstage16(sm[(s + 1) & 1].BsH, sm[(s + 1) & 1].BsL,
                             pb0, pb1, pb2, pb3, tid);
            __syncthreads();
        }
    }

    int ma, na;
    #pragma unroll
    for (ma = 0; ma < 4; ma++) {
        long r = row0 + m0w + ma * 16 + g;
        #pragma unroll
        for (na = 0; na < 8; na++) {
            long c = col0 + n0w + na * 8 + 2 * t;
            C[r * S_DIM + c]           = acc[ma][na][0] * scale;
            C[r * S_DIM + c + 1]       = acc[ma][na][1] * scale;
            C[(r + 8) * S_DIM + c]     = acc[ma][na][2] * scale;
            C[(r + 8) * S_DIM + c + 1] = acc[ma][na][3] * scale;
        }
    }
}

// ---------------- attn_out = X + sum_h attn[h] @ V[h], bounded k ------------
__global__ void __launch_bounds__(128) mma_attn_av(
    const float *ATT, const float *V, const float *X, float *C)
{
    __shared__ SmemTiles sm[2];

    int tid = threadIdx.x;
    int lane = tid & 31;
    int warp = tid >> 5;
    int g = lane >> 2;
    int t = lane & 3;
    int m0w = (warp >> 1) * 64;
    int n0w = (warp & 1) * 64;
    long row0 = (long)blockIdx.y * 128;
    long col0 = (long)blockIdx.x * 128;

    int bk2 = tid >> 4;
    int bnc = (tid & 15) * 8;

    int nk = ((int)blockIdx.y + 1) * 8;   // k16 steps per head
    int total = H_DIM * nk;

    float acc[4][8][4];
    int i0, i1, i2;
    #pragma unroll
    for (i0 = 0; i0 < 4; i0++)
        #pragma unroll
        for (i1 = 0; i1 < 8; i1++)
            #pragma unroll
            for (i2 = 0; i2 < 4; i2++)
                acc[i0][i1][i2] = 0.0f;

    float4 pa0, pa1, pa2, pa3, pb00, pb01, pb10, pb11;
    const float *ap0 = ATT + (row0 + tid) * (long)S_DIM;
    const float *bp0 = V + (long)(2 * bk2) * E_DIM + col0 + bnc;
    pa0 = *(const float4 *)(ap0);
    pa1 = *(const float4 *)(ap0 + 4);
    pa2 = *(const float4 *)(ap0 + 8);
    pa3 = *(const float4 *)(ap0 + 12);
    pb00 = *(const float4 *)(bp0);
    pb01 = *(const float4 *)(bp0 + 4);
    pb10 = *(const float4 *)(bp0 + E_DIM);
    pb11 = *(const float4 *)(bp0 + E_DIM + 4);

    store_colstage16(sm[0].AsH, sm[0].AsL, pa0, pa1, pa2, pa3, tid);
    store_rowstage8(&sm[0], pb00, pb01, pb10, pb11, bk2, bnc);
    __syncthreads();

    int h = 0;
    int ks = 0;
    int it;
    for (it = 0; it < total; it++) {
        int more = (it + 1 < total) ? 1 : 0;
        int h2 = h;
        int k2 = ks + 1;
        if (k2 == nk) {
            k2 = 0;
            h2 = h2 + 1;
        }
        if (more) {
            const float *ap2 = ATT + (long)h2 * S_DIM * S_DIM
                             + (row0 + tid) * (long)S_DIM + k2 * 16;
            const float *bp2 = V + (long)h2 * S_DIM * E_DIM
                             + (long)(k2 * 16 + 2 * bk2) * E_DIM + col0 + bnc;
            pa0 = *(const float4 *)(ap2);
            pa1 = *(const float4 *)(ap2 + 4);
            pa2 = *(const float4 *)(ap2 + 8);
            pa3 = *(const float4 *)(ap2 + 12);
            pb00 = *(const float4 *)(bp2);
            pb01 = *(const float4 *)(bp2 + 4);
            pb10 = *(const float4 *)(bp2 + E_DIM);
            pb11 = *(const float4 *)(bp2 + E_DIM + 4);
        }
        compute_stage(&sm[it & 1], acc, m0w, n0w, g, t);
        if (more) {
            store_colstage16(sm[(it + 1) & 1].AsH, sm[(it + 1) & 1].AsL,
                             pa0, pa1, pa2, pa3, tid);
            store_rowstage8(&sm[(it + 1) & 1], pb00, pb01, pb10, pb11, bk2, bnc);
            __syncthreads();
        }
        h = h2;
        ks = k2;
    }

    int ma, na;
    #pragma unroll
    for (ma = 0; ma < 4; ma++) {
        long r = row0 + m0w + ma * 16 + g;
        #pragma unroll
        for (na = 0; na < 8; na++) {
            long c = col0 + n0w + na * 8 + 2 * t;
            C[r * E_DIM + c]           = acc[ma][na][0] + X[r * E_DIM + c];
            C[r * E_DIM + c + 1]       = acc[ma][na][1] + X[r * E_DIM + c + 1];
            C[(r + 8) * E_DIM + c]     = acc[ma][na][2] + X[(r + 8) * E_DIM + c];
            C[(r + 8) * E_DIM + c + 1] = acc[ma][na][3] + X[(r + 8) * E_DIM + c + 1];
        }
    }
}

// ---------------- causal row softmax, in place, zeros above diagonal --------
__global__ void __launch_bounds__(256) softmax_causal(float *sc)
{
    __shared__ float buf[S_DIM];
    __shared__ float red[256];

    int s = blockIdx.x;
    int h = blockIdx.y;
    float *row = sc + ((long)h * S_DIM + s) * (long)S_DIM;
    int tid = threadIdx.x;
    int len = s + 1;
    int i;
    int st;

    float lmax = -INFINITY;
    for (i = tid; i < len; i += 256) {
        float v = row[i];
        buf[i] = v;
        lmax = fmaxf(lmax, v);
    }
    red[tid] = lmax;
    __syncthreads();
    for (st = 128; st > 0; st >>= 1) {
        if (tid < st) red[tid] = fmaxf(red[tid], red[tid + st]);
        __syncthreads();
    }
    float m = red[0];
    __syncthreads();

    float lsum = 0.0f;
    for (i = tid; i < len; i += 256) {
        float e = __expf(buf[i] - m);
        buf[i] = e;
        lsum += e;
    }
    red[tid] = lsum;
    __syncthreads();
    for (st = 128; st > 0; st >>= 1) {
        if (tid < st) red[tid] = red[tid] + red[tid + st];
        __syncthreads();
    }
    float inv = 1.0f / red[0];
    for (i = tid; i < S_DIM; i += 256) {
        float o = 0.0f;
        if (i < len) o = buf[i] * inv;
        row[i] = o;
    }
}

// ---------------- global LayerNorm (mean/var over ALL S*E elements) ---------
__global__ void __launch_bounds__(256) ln_reduce(const float *y, double *part)
{
    __shared__ double sd[256];
    __shared__ double sq[256];

    double s = 0.0;
    double ss = 0.0;
    long stride = (long)gridDim.x * 256;
    long i;
    int st;
    for (i = (long)blockIdx.x * 256 + threadIdx.x; i < NTOT; i += stride) {
        double v = (double)y[i];
        s += v;
        ss += v * v;
    }
    sd[threadIdx.x] = s;
    sq[threadIdx.x] = ss;
    __syncthreads();
    for (st = 128; st > 0; st >>= 1) {
        if (threadIdx.x < st) {
            sd[threadIdx.x] = sd[threadIdx.x] + sd[threadIdx.x + st];
            sq[threadIdx.x] = sq[threadIdx.x] + sq[threadIdx.x + st];
        }
        __syncthreads();
    }
    if (threadIdx.x == 0) {
        part[blockIdx.x] = sd[0];
        part[1024 + blockIdx.x] = sq[0];
    }
}

__global__ void __launch_bounds__(256) ln_finalize(const double *part, float *stats)
{
    __shared__ double sd[256];
    __shared__ double sq[256];

    double s = 0.0;
    double ss = 0.0;
    int i;
    int st;
    for (i = threadIdx.x; i < 1024; i += 256) {
        s += part[i];
        ss += part[1024 + i];
    }
    sd[threadIdx.x] = s;
    sq[threadIdx.x] = ss;
    __syncthreads();
    for (st = 128; st > 0; st >>= 1) {
        if (threadIdx.x < st) {
            sd[threadIdx.x] = sd[threadIdx.x] + sd[threadIdx.x + st];
            sq[threadIdx.x] = sq[threadIdx.x] + sq[threadIdx.x + st];
        }
        __syncthreads();
    }
    if (threadIdx.x == 0) {
        double mean = sd[0] / (double)NTOT;
        double var = sq[0] / (double)NTOT - mean * mean;
        stats[0] = (float)mean;
        stats[1] = (float)(1.0 / sqrt(var + (double)EPS));
    }
}

__global__ void __launch_bounds__(256) ln_apply(
    const float *y, const float *g, const float *b,
    const float *st, float *o)
{
    float m = st[0];
    float is = st[1];
    long stride = (long)gridDim.x * 256;
    long i;
    for (i = (long)blockIdx.x * 256 + threadIdx.x; i < NTOT; i += stride) {
        o[i] = (y[i] - m) * is * g[i] + b[i];
    }
}

// ---------------- host orchestration ----------------------------------------
extern "C" void kernel_launch(void* const* d_in, const int* in_sizes, int n_in,
                              void* d_out, int out_size)
{
    const float *x  = (const float *)d_in[0];
    const float *Wq = (const float *)d_in[1];
    const float *bq = (const float *)d_in[2];
    const float *Wk = (const float *)d_in[3];
    const float *bk = (const float *)d_in[4];
    const float *Wv = (const float *)d_in[5];
    const float *bv = (const float *)d_in[6];
    const float *lg = (const float *)d_in[7];
    const float *lb = (const float *)d_in[8];
    const float *W1 = (const float *)d_in[9];
    const float *b1 = (const float *)d_in[10];
    const float *W2 = (const float *)d_in[11];
    const float *b2 = (const float *)d_in[12];
    float *out = (float *)d_out;

    void *vq = 0;
    void *vk = 0;
    void *vv = 0;
    void *vsc = 0;
    void *vy = 0;
    void *vh = 0;
    void *vff = 0;
    void *vpart = 0;
    void *vstats = 0;
    cudaGetSymbolAddress(&vq,  g_q);
    cudaGetSymbolAddress(&vk,  g_k);
    cudaGetSymbolAddress(&vv,  g_v);
    cudaGetSymbolAddress(&vsc, g_sc);
    cudaGetSymbolAddress(&vy,  g_y);
    cudaGetSymbolAddress(&vh,  g_h);
    cudaGetSymbolAddress(&vff, g_ff);
    cudaGetSymbolAddress(&vpart,  g_part);
    cudaGetSymbolAddress(&vstats, g_stats);
    float *pq = (float *)vq;
    float *pk = (float *)vk;
    float *pv = (float *)vv;
    float *psc = (float *)vsc;
    float *py = (float *)vy;
    float *ph = (float *)vh;
    float *pff = (float *)vff;
    double *ppart = (double *)vpart;
    float *pstats = (float *)vstats;

    dim3 blkm(128, 1, 1);
    dim3 blk(256, 1, 1);
    float scale = 1.0f / sqrtf((float)KD_DIM);

    // Q/K/V projections (per-head, batched over blockIdx.z)
    {
        dim3 gq(1, S_DIM / 128, H_DIM);
        mma_gemm_nn<<<gq, blkm>>>(x, Wq, bq, (const float *)0, pq,
            E_DIM, KD_DIM, (long)E_DIM * KD_DIM, (long)KD_DIM,
            (long)S_DIM * KD_DIM, 0);
        mma_gemm_nn<<<gq, blkm>>>(x, Wk, bk, (const float *)0, pk,
            E_DIM, KD_DIM, (long)E_DIM * KD_DIM, (long)KD_DIM,
            (long)S_DIM * KD_DIM, 0);
    }
    {
        dim3 gv(E_DIM / 128, S_DIM / 128, H_DIM);
        mma_gemm_nn<<<gv, blkm>>>(x, Wv, bv, (const float *)0, pv,
            E_DIM, E_DIM, (long)E_DIM * E_DIM, (long)E_DIM,
            (long)S_DIM * E_DIM, 0);
    }

    // scores + causal softmax
    {
        dim3 gs(S_DIM / 128, S_DIM / 128, H_DIM);
        mma_gemm_nt_causal<<<gs, blkm>>>(pq, pk, psc, scale);
    }
    {
        dim3 gsm(S_DIM, H_DIM, 1);
        softmax_causal<<<gsm, blk>>>(psc);
    }

    // attn @ V summed over heads, + residual x
    {
        dim3 ga(E_DIM / 128, S_DIM / 128, 1);
        mma_attn_av<<<ga, blkm>>>(psc, pv, x, py);
    }

    // LN1 (global)
    ln_reduce<<<1024, blk>>>(py, ppart);
    ln_finalize<<<1, blk>>>(ppart, pstats);
    ln_apply<<<4096, blk>>>(py, lg, lb, pstats, ph);

    // FFN
    {
        dim3 g1(FF_DIM / 128, S_DIM / 128, 1);
        mma_gemm_nn<<<g1, blkm>>>(ph, W1, b1, (const float *)0, pff,
            E_DIM, FF_DIM, 0L, 0L, 0L, 1);
        dim3 g2(E_DIM / 128, S_DIM / 128, 1);
        mma_gemm_nn<<<g2, blkm>>>(pff, W2, b2, ph, py,
            FF_DIM, E_DIM, 0L, 0L, 0L, 0);
    }

    // LN2 -> output
    ln_reduce<<<1024, blk>>>(py, ppart);
    ln_finalize<<<1, blk>>>(ppart, pstats);
    ln_apply<<<4096, blk>>>(py, lg, lb, pstats, out);
}

// round 12
// speedup vs baseline: 1.1067x; 1.1067x over previous
#include <cuda_runtime.h>
#include <cuda_bf16.h>
#include <stdint.h>
#include <math.h>

// Problem dims
#define S_DIM 2048
#define E_DIM 2048
#define H_DIM 16
#define KD_DIM 128
#define FF_DIM 8192
#define EPS 1e-5f
#define NTOT (2048L * 2048L)

// ---------------- scratch (device globals; no allocations allowed) ----------
__device__ float  g_q [(long)H_DIM * S_DIM * KD_DIM];
__device__ float  g_k [(long)H_DIM * S_DIM * KD_DIM];
__device__ float  g_ax[(long)S_DIM * E_DIM];            // attnx per-head buffer
__device__ float  g_sc[(long)H_DIM * S_DIM * S_DIM];
__device__ float  g_y [(long)S_DIM * E_DIM];
__device__ float  g_h [(long)S_DIM * E_DIM];
__device__ float  g_ff[(long)S_DIM * FF_DIM];
__device__ double g_part[2048];
__device__ float  g_stats[2];

// =====================  bf16-split tensor-core GEMM engine  =================
// Block tile 128x128, BK=16 (one m16n8k16 step per stage), 256 threads,
// warp grid 2(M) x 4(N), warp tile 64x32 -> 4x4 mma atoms per warp.
// A = Ah + Al, B = Bh + Bl (bf16 each); acc += AhBh + AhBl + AlBh.
// Double-buffered smem stages: one __syncthreads per k16 stage.
#define PITCH 136

struct SmemTiles {
    uint32_t AsH[8][PITCH];
    uint32_t AsL[8][PITCH];
    uint32_t BsH[8][PITCH];
    uint32_t BsL[8][PITCH];
};

__device__ __forceinline__ void split_pair(float f0, float f1,
                                           uint32_t &hi, uint32_t &lo)
{
    __nv_bfloat16 h0 = __float2bfloat16_rn(f0);
    __nv_bfloat16 h1 = __float2bfloat16_rn(f1);
    __nv_bfloat16 l0 = __float2bfloat16_rn(f0 - __bfloat162float(h0));
    __nv_bfloat16 l1 = __float2bfloat16_rn(f1 - __bfloat162float(h1));
    unsigned short u0 = __bfloat16_as_ushort(h0);
    unsigned short u1 = __bfloat16_as_ushort(h1);
    unsigned short w0 = __bfloat16_as_ushort(l0);
    unsigned short w1 = __bfloat16_as_ushort(l1);
    hi = (uint32_t)u0 | ((uint32_t)u1 << 16);
    lo = (uint32_t)w0 | ((uint32_t)w1 << 16);
}

__device__ __forceinline__ void mma16816(float *c, const uint32_t *a,
                                         const uint32_t *b)
{
    asm volatile(
        "mma.sync.aligned.m16n8k16.row.col.f32.bf16.bf16.f32 "
        "{%0,%1,%2,%3},{%4,%5,%6,%7},{%8,%9},{%0,%1,%2,%3};\n"
        : "+f"(c[0]), "+f"(c[1]), "+f"(c[2]), "+f"(c[3])
        : "r"(a[0]), "r"(a[1]), "r"(a[2]), "r"(a[3]), "r"(b[0]), "r"(b[1]));
}

// one k16 step for a 64x32 warp tile
__device__ __forceinline__ void compute_stage(const SmemTiles *sm,
    float acc[4][4][4], int m0w, int n0w, int g, int t)
{
    uint32_t bh[4][2];
    uint32_t bl[4][2];
    int na, ma;
    #pragma unroll
    for (na = 0; na < 4; na++) {
        int c = n0w + na * 8 + g;
        bh[na][0] = sm->BsH[t][c];
        bh[na][1] = sm->BsH[t + 4][c];
        bl[na][0] = sm->BsL[t][c];
        bl[na][1] = sm->BsL[t + 4][c];
    }
    #pragma unroll
    for (ma = 0; ma < 4; ma++) {
        int r0 = m0w + ma * 16 + g;
        uint32_t ah[4];
        uint32_t al[4];
        ah[0] = sm->AsH[t][r0];
        ah[1] = sm->AsH[t][r0 + 8];
        ah[2] = sm->AsH[t + 4][r0];
        ah[3] = sm->AsH[t + 4][r0 + 8];
        al[0] = sm->AsL[t][r0];
        al[1] = sm->AsL[t][r0 + 8];
        al[2] = sm->AsL[t + 4][r0];
        al[3] = sm->AsL[t + 4][r0 + 8];
        #pragma unroll
        for (na = 0; na < 4; na++) {
            mma16816(acc[ma][na], ah, bh[na]);
            mma16816(acc[ma][na], ah, bl[na]);
            mma16816(acc[ma][na], al, bh[na]);
        }
    }
}

// stage a row-major [128 x 16] tile "column-wise": thread owns row = tid>>1,
// k-halfword base = (tid&1)*8 floats; dest smem rows k2b..k2b+3
__device__ __forceinline__ void store_colstage(uint32_t (*Hi)[PITCH],
    uint32_t (*Lo)[PITCH], float4 v0, float4 v1, int k2b, int row)
{
    split_pair(v0.x, v0.y, Hi[k2b + 0][row], Lo[k2b + 0][row]);
    split_pair(v0.z, v0.w, Hi[k2b + 1][row], Lo[k2b + 1][row]);
    split_pair(v1.x, v1.y, Hi[k2b + 2][row], Lo[k2b + 2][row]);
    split_pair(v1.z, v1.w, Hi[k2b + 3][row], Lo[k2b + 3][row]);
}

// stage a row-major [16 x 128] B tile: thread owns k2 = tid>>5, col = (tid&31)*4
__device__ __forceinline__ void store_rowstage(SmemTiles *sm,
    float4 r0, float4 r1, int k2, int nc)
{
    uint32_t h0, h1, h2, h3, l0, l1, l2, l3;
    split_pair(r0.x, r1.x, h0, l0);
    split_pair(r0.y, r1.y, h1, l1);
    split_pair(r0.z, r1.z, h2, l2);
    split_pair(r0.w, r1.w, h3, l3);
    sm->BsH[k2][nc + 0] = h0;
    sm->BsH[k2][nc + 1] = h1;
    sm->BsH[k2][nc + 2] = h2;
    sm->BsH[k2][nc + 3] = h3;
    sm->BsL[k2][nc + 0] = l0;
    sm->BsL[k2][nc + 1] = l1;
    sm->BsL[k2][nc + 2] = l2;
    sm->BsL[k2][nc + 3] = l3;
}

// ---------------- C = A[M,K] @ B[K,N] (+bias)(+resid)(relu), batched z ------
// causalA != 0: A cols beyond (blockIdx.y+1)*128 are exactly zero -> K loop
// bounded at (blockIdx.y+1)*128.
__global__ void __launch_bounds__(256) mma_gemm_nn(
    const float *Ag, const float *Bg,
    const float *bias, const float *resid,
    float *Cg, int K, int N,
    long sA, long sB, long sBias, long sC, int relu, int causalA)
{
    __shared__ SmemTiles sm[2];

    const float *A = Ag + (long)blockIdx.z * sA;
    const float *B = Bg + (long)blockIdx.z * sB;
    const float *bi = (bias != 0) ? (bias + (long)blockIdx.z * sBias) : (const float *)0;
    float *C = Cg + (long)blockIdx.z * sC;

    int tid = threadIdx.x;
    int lane = tid & 31;
    int warp = tid >> 5;
    int g = lane >> 2;
    int t = lane & 3;
    int m0w = (warp >> 2) * 64;
    int n0w = (warp & 3) * 32;
    long row0 = (long)blockIdx.y * 128;
    long col0 = (long)blockIdx.x * 128;

    int arow = tid >> 1;
    int akc = (tid & 1) * 8;
    int ak2 = (tid & 1) * 4;
    int bkr = tid >> 5;
    int bnc = (tid & 31) * 4;

    float acc[4][4][4];
    int i0, i1, i2;
    #pragma unroll
    for (i0 = 0; i0 < 4; i0++)
        #pragma unroll
        for (i1 = 0; i1 < 4; i1++)
            #pragma unroll
            for (i2 = 0; i2 < 4; i2++)
                acc[i0][i1][i2] = 0.0f;

    const float *aptr = A + (row0 + arow) * (long)K + akc;
    const float *bptr = B + (long)(2 * bkr) * N + col0 + bnc;

    float4 pa0 = *(const float4 *)(aptr);
    float4 pa1 = *(const float4 *)(aptr + 4);
    float4 pb0 = *(const float4 *)(bptr);
    float4 pb1 = *(const float4 *)(bptr + N);

    store_colstage(sm[0].AsH, sm[0].AsL, pa0, pa1, ak2, arow);
    store_rowstage(&sm[0], pb0, pb1, bkr, bnc);
    __syncthreads();

    int nsteps = (causalA != 0) ? (((int)blockIdx.y + 1) * 8) : (K / 16);
    int s;
    for (s = 0; s < nsteps; s++) {
        int more = (s + 1 < nsteps) ? 1 : 0;
        if (more) {
            const float *ap2 = aptr + (s + 1) * 16;
            const float *bp2 = bptr + (long)(s + 1) * 16 * N;
            pa0 = *(const float4 *)(ap2);
            pa1 = *(const float4 *)(ap2 + 4);
            pb0 = *(const float4 *)(bp2);
            pb1 = *(const float4 *)(bp2 + N);
        }
        compute_stage(&sm[s & 1], acc, m0w, n0w, g, t);
        if (more) {
            store_colstage(sm[(s + 1) & 1].AsH, sm[(s + 1) & 1].AsL,
                           pa0, pa1, ak2, arow);
            store_rowstage(&sm[(s + 1) & 1], pb0, pb1, bkr, bnc);
            __syncthreads();
        }
    }

    int ma, na;
    #pragma unroll
    for (ma = 0; ma < 4; ma++) {
        long r = row0 + m0w + ma * 16 + g;
        #pragma unroll
        for (na = 0; na < 4; na++) {
            long c = col0 + n0w + na * 8 + 2 * t;
            float b0 = 0.0f;
            float b1 = 0.0f;
            if (bi != 0) {
                b0 = bi[c];
                b1 = bi[c + 1];
            }
            float v0 = acc[ma][na][0] + b0;
            float v1 = acc[ma][na][1] + b1;
            float w0 = acc[ma][na][2] + b0;
            float w1 = acc[ma][na][3] + b1;
            if (resid != 0) {
                v0 += resid[r * N + c];
                v1 += resid[r * N + c + 1];
                w0 += resid[(r + 8) * N + c];
                w1 += resid[(r + 8) * N + c + 1];
            }
            if (relu != 0) {
                v0 = fmaxf(v0, 0.0f);
                v1 = fmaxf(v1, 0.0f);
                w0 = fmaxf(w0, 0.0f);
                w1 = fmaxf(w1, 0.0f);
            }
            C[r * N + c]           = v0;
            C[r * N + c + 1]       = v1;
            C[(r + 8) * N + c]     = w0;
            C[(r + 8) * N + c + 1] = w1;
        }
    }
}

// ---------------- scores = (Q @ K^T)/sqrt(KD), causal block skip ------------
__global__ void __launch_bounds__(256) mma_gemm_nt_causal(
    const float *Qg, const float *Kg, float *SCg, float scale)
{
    __shared__ SmemTiles sm[2];

    if (blockIdx.x > blockIdx.y) return;
    const float *A = Qg + (long)blockIdx.z * S_DIM * KD_DIM;
    const float *B = Kg + (long)blockIdx.z * S_DIM * KD_DIM;
    float *C = SCg + (long)blockIdx.z * S_DIM * (long)S_DIM;

    int tid = threadIdx.x;
    int lane = tid & 31;
    int warp = tid >> 5;
    int g = lane >> 2;
    int t = lane & 3;
    int m0w = (warp >> 2) * 64;
    int n0w = (warp & 3) * 32;
    long row0 = (long)blockIdx.y * 128;
    long col0 = (long)blockIdx.x * 128;

    int arow = tid >> 1;
    int akc = (tid & 1) * 8;
    int ak2 = (tid & 1) * 4;

    float acc[4][4][4];
    int i0, i1, i2;
    #pragma unroll
    for (i0 = 0; i0 < 4; i0++)
        #pragma unroll
        for (i1 = 0; i1 < 4; i1++)
            #pragma unroll
            for (i2 = 0; i2 < 4; i2++)
                acc[i0][i1][i2] = 0.0f;

    const float *aptr = A + (row0 + arow) * (long)KD_DIM + akc;
    const float *bptr = B + (col0 + arow) * (long)KD_DIM + akc;

    float4 pa0 = *(const float4 *)(aptr);
    float4 pa1 = *(const float4 *)(aptr + 4);
    float4 pb0 = *(const float4 *)(bptr);
    float4 pb1 = *(const float4 *)(bptr + 4);

    store_colstage(sm[0].AsH, sm[0].AsL, pa0, pa1, ak2, arow);
    store_colstage(sm[0].BsH, sm[0].BsL, pb0, pb1, ak2, arow);
    __syncthreads();

    int nsteps = KD_DIM / 16;
    int s;
    for (s = 0; s < nsteps; s++) {
        int more = (s + 1 < nsteps) ? 1 : 0;
        if (more) {
            const float *ap2 = aptr + (s + 1) * 16;
            const float *bp2 = bptr + (s + 1) * 16;
            pa0 = *(const float4 *)(ap2);
            pa1 = *(const float4 *)(ap2 + 4);
            pb0 = *(const float4 *)(bp2);
            pb1 = *(const float4 *)(bp2 + 4);
        }
        compute_stage(&sm[s & 1], acc, m0w, n0w, g, t);
        if (more) {
            store_colstage(sm[(s + 1) & 1].AsH, sm[(s + 1) & 1].AsL,
                           pa0, pa1, ak2, arow);
            store_colstage(sm[(s + 1) & 1].BsH, sm[(s + 1) & 1].BsL,
                           pb0, pb1, ak2, arow);
            __syncthreads();
        }
    }

    int ma, na;
    #pragma unroll
    for (ma = 0; ma < 4; ma++) {
        long r = row0 + m0w + ma * 16 + g;
        #pragma unroll
        for (na = 0; na < 4; na++) {
            long c = col0 + n0w + na * 8 + 2 * t;
            C[r * S_DIM + c]           = acc[ma][na][0] * scale;
            C[r * S_DIM + c + 1]       = acc[ma][na][1] * scale;
            C[(r + 8) * S_DIM + c]     = acc[ma][na][2] * scale;
            C[(r + 8) * S_DIM + c + 1] = acc[ma][na][3] * scale;
        }
    }
}

// ---------------- causal row softmax, in place, zeros above diagonal --------
__global__ void __launch_bounds__(256) softmax_causal(float *sc)
{
    __shared__ float buf[S_DIM];
    __shared__ float red[256];

    int s = blockIdx.x;
    int h = blockIdx.y;
    float *row = sc + ((long)h * S_DIM + s) * (long)S_DIM;
    int tid = threadIdx.x;
    int len = s + 1;
    int i;
    int st;

    float lmax = -INFINITY;
    for (i = tid; i < len; i += 256) {
        float v = row[i];
        buf[i] = v;
        lmax = fmaxf(lmax, v);
    }
    red[tid] = lmax;
    __syncthreads();
    for (st = 128; st > 0; st >>= 1) {
        if (tid < st) red[tid] = fmaxf(red[tid], red[tid + st]);
        __syncthreads();
    }
    float m = red[0];
    __syncthreads();

    float lsum = 0.0f;
    for (i = tid; i < len; i += 256) {
        float e = __expf(buf[i] - m);
        buf[i] = e;
        lsum += e;
    }
    red[tid] = lsum;
    __syncthreads();
    for (st = 128; st > 0; st >>= 1) {
        if (tid < st) red[tid] = red[tid] + red[tid + st];
        __syncthreads();
    }
    float inv = 1.0f / red[0];
    for (i = tid; i < S_DIM; i += 256) {
        float o = 0.0f;
        if (i < len) o = buf[i] * inv;
        row[i] = o;
    }
}

// ---------------- global LayerNorm (mean/var over ALL S*E elements) ---------
__global__ void __launch_bounds__(256) ln_reduce(const float *y, double *part)
{
    __shared__ double sd[256];
    __shared__ double sq[256];

    double s = 0.0;
    double ss = 0.0;
    long stride = (long)gridDim.x * 256;
    long i;
    int st;
    for (i = (long)blockIdx.x * 256 + threadIdx.x; i < NTOT; i += stride) {
        double v = (double)y[i];
        s += v;
        ss += v * v;
    }
    sd[threadIdx.x] = s;
    sq[threadIdx.x] = ss;
    __syncthreads();
    for (st = 128; st > 0; st >>= 1) {
        if (threadIdx.x < st) {
            sd[threadIdx.x] = sd[threadIdx.x] + sd[threadIdx.x + st];
            sq[threadIdx.x] = sq[threadIdx.x] + sq[threadIdx.x + st];
        }
        __syncthreads();
    }
    if (threadIdx.x == 0) {
        part[blockIdx.x] = sd[0];
        part[1024 + blockIdx.x] = sq[0];
    }
}

__global__ void __launch_bounds__(256) ln_finalize(const double *part, float *stats)
{
    __shared__ double sd[256];
    __shared__ double sq[256];

    double s = 0.0;
    double ss = 0.0;
    int i;
    int st;
    for (i = threadIdx.x; i < 1024; i += 256) {
        s += part[i];
        ss += part[1024 + i];
    }
    sd[threadIdx.x] = s;
    sq[threadIdx.x] = ss;
    __syncthreads();
    for (st = 128; st > 0; st >>= 1) {
        if (threadIdx.x < st) {
            sd[threadIdx.x] = sd[threadIdx.x] + sd[threadIdx.x + st];
            sq[threadIdx.x] = sq[threadIdx.x] + sq[threadIdx.x + st];
        }
        __syncthreads();
    }
    if (threadIdx.x == 0) {
        double mean = sd[0] / (double)NTOT;
        double var = sq[0] / (double)NTOT - mean * mean;
        stats[0] = (float)mean;
        stats[1] = (float)(1.0 / sqrt(var + (double)EPS));
    }
}

__global__ void __launch_bounds__(256) ln_apply(
    const float *y, const float *g, const float *b,
    const float *st, float *o)
{
    float m = st[0];
    float is = st[1];
    long stride = (long)gridDim.x * 256;
    long i;
    for (i = (long)blockIdx.x * 256 + threadIdx.x; i < NTOT; i += stride) {
        o[i] = (y[i] - m) * is * g[i] + b[i];
    }
}

// ---------------- host orchestration ----------------------------------------
extern "C" void kernel_launch(void* const* d_in, const int* in_sizes, int n_in,
                              void* d_out, int out_size)
{
    const float *x  = (const float *)d_in[0];
    const float *Wq = (const float *)d_in[1];
    const float *bq = (const float *)d_in[2];
    const float *Wk = (const float *)d_in[3];
    const float *bk = (const float *)d_in[4];
    const float *Wv = (const float *)d_in[5];
    const float *bv = (const float *)d_in[6];
    const float *lg = (const float *)d_in[7];
    const float *lb = (const float *)d_in[8];
    const float *W1 = (const float *)d_in[9];
    const float *b1 = (const float *)d_in[10];
    const float *W2 = (const float *)d_in[11];
    const float *b2 = (const float *)d_in[12];
    float *out = (float *)d_out;

    void *vq = 0;
    void *vk = 0;
    void *vax = 0;
    void *vsc = 0;
    void *vy = 0;
    void *vh = 0;
    void *vff = 0;
    void *vpart = 0;
    void *vstats = 0;
    cudaGetSymbolAddress(&vq,  g_q);
    cudaGetSymbolAddress(&vk,  g_k);
    cudaGetSymbolAddress(&vax, g_ax);
    cudaGetSymbolAddress(&vsc, g_sc);
    cudaGetSymbolAddress(&vy,  g_y);
    cudaGetSymbolAddress(&vh,  g_h);
    cudaGetSymbolAddress(&vff, g_ff);
    cudaGetSymbolAddress(&vpart,  g_part);
    cudaGetSymbolAddress(&vstats, g_stats);
    float *pq = (float *)vq;
    float *pk = (float *)vk;
    float *pax = (float *)vax;
    float *psc = (float *)vsc;
    float *py = (float *)vy;
    float *ph = (float *)vh;
    float *pff = (float *)vff;
    double *ppart = (double *)vpart;
    float *pstats = (float *)vstats;

    dim3 blk(256, 1, 1);
    float scale = 1.0f / sqrtf((float)KD_DIM);
    int h;

    // Q/K projections (per-head, batched over blockIdx.z)
    {
        dim3 gq(1, S_DIM / 128, H_DIM);
        mma_gemm_nn<<<gq, blk>>>(x, Wq, bq, (const float *)0, pq,
            E_DIM, KD_DIM, 0L, (long)E_DIM * KD_DIM, (long)KD_DIM,
            (long)S_DIM * KD_DIM, 0, 0);
        mma_gemm_nn<<<gq, blk>>>(x, Wk, bk, (const float *)0, pk,
            E_DIM, KD_DIM, 0L, (long)E_DIM * KD_DIM, (long)KD_DIM,
            (long)S_DIM * KD_DIM, 0, 0);
    }

    // scores + causal softmax
    {
        dim3 gs(S_DIM / 128, S_DIM / 128, H_DIM);
        mma_gemm_nt_causal<<<gs, blk>>>(pq, pk, psc, scale);
    }
    {
        dim3 gsm(S_DIM, H_DIM, 1);
        softmax_causal<<<gsm, blk>>>(psc);
    }

    // Attention value path, refactored:
    //   y = x + sum_h [ (attn[h] @ x) @ Wv[h] + bv[h] ]
    // (rows of attn sum to 1, so the bv term distributes out of the attn matmul)
    // attnx stays L2-resident between the paired launches; Wv[h] (16MB) fits L2.
    {
        dim3 ga(E_DIM / 128, S_DIM / 128, 1);
        for (h = 0; h < H_DIM; h++) {
            mma_gemm_nn<<<ga, blk>>>(psc + (long)h * S_DIM * S_DIM, x,
                (const float *)0, (const float *)0, pax,
                S_DIM, E_DIM, 0L, 0L, 0L, 0L, 0, 1 /*causalA*/);
            mma_gemm_nn<<<ga, blk>>>(pax, Wv + (long)h * E_DIM * E_DIM,
                bv + (long)h * E_DIM, (h == 0) ? x : py, py,
                E_DIM, E_DIM, 0L, 0L, 0L, 0L, 0, 0);
        }
    }

    // LN1 (global)
    ln_reduce<<<1024, blk>>>(py, ppart);
    ln_finalize<<<1, blk>>>(ppart, pstats);
    ln_apply<<<4096, blk>>>(py, lg, lb, pstats, ph);

    // FFN
    {
        dim3 g1(FF_DIM / 128, S_DIM / 128, 1);
        mma_gemm_nn<<<g1, blk>>>(ph, W1, b1, (const float *)0, pff,
            E_DIM, FF_DIM, 0L, 0L, 0L, 0L, 1, 0);
        dim3 g2(E_DIM / 128, S_DIM / 128, 1);
        mma_gemm_nn<<<g2, blk>>>(pff, W2, b2, ph, py,
            FF_DIM, E_DIM, 0L, 0L, 0L, 0L, 0, 0);
    }

    // LN2 -> output
    ln_reduce<<<1024, blk>>>(py, ppart);
    ln_finalize<<<1, blk>>>(ppart, pstats);
    ln_apply<<<4096, blk>>>(py, lg, lb, pstats, out);
}

// round 14
// speedup vs baseline: 1.5255x; 1.3785x over previous
#include <cuda_runtime.h>
#include <cuda_bf16.h>
#include <stdint.h>
#include <math.h>

// Problem dims
#define S_DIM 2048
#define E_DIM 2048
#define H_DIM 16
#define KD_DIM 128
#define FF_DIM 8192
#define EPS 1e-5f
#define NTOT (2048L * 2048L)

// ---------------- scratch (device globals; no allocations allowed) ----------
// fp32 intermediates
__device__ float    g_v  [(long)H_DIM * S_DIM * E_DIM];
__device__ float    g_sc [(long)H_DIM * S_DIM * S_DIM];
__device__ float    g_y  [(long)S_DIM * E_DIM];
__device__ float    g_h  [(long)S_DIM * E_DIM];
__device__ float    g_pt [4L * S_DIM * E_DIM];
__device__ double   g_part[2048];
__device__ float    g_stats[2];
// paired-bf16 hi/lo operand buffers (uint32 = bf16x2)
__device__ uint32_t g_xhi [(long)S_DIM * E_DIM / 2];
__device__ uint32_t g_xlo [(long)S_DIM * E_DIM / 2];
__device__ uint32_t g_wqhi[(long)H_DIM * E_DIM * KD_DIM / 2];
__device__ uint32_t g_wqlo[(long)H_DIM * E_DIM * KD_DIM / 2];
__device__ uint32_t g_wkhi[(long)H_DIM * E_DIM * KD_DIM / 2];
__device__ uint32_t g_wklo[(long)H_DIM * E_DIM * KD_DIM / 2];
__device__ uint32_t g_wvhi[(long)H_DIM * E_DIM * E_DIM / 2];
__device__ uint32_t g_wvlo[(long)H_DIM * E_DIM * E_DIM / 2];
__device__ uint32_t g_w1hi[(long)E_DIM * FF_DIM / 2];
__device__ uint32_t g_w1lo[(long)E_DIM * FF_DIM / 2];
__device__ uint32_t g_w2hi[(long)FF_DIM * E_DIM / 2];
__device__ uint32_t g_w2lo[(long)FF_DIM * E_DIM / 2];
__device__ uint32_t g_qhi [(long)H_DIM * S_DIM * KD_DIM / 2];
__device__ uint32_t g_qlo [(long)H_DIM * S_DIM * KD_DIM / 2];
__device__ uint32_t g_khi [(long)H_DIM * S_DIM * KD_DIM / 2];
__device__ uint32_t g_klo [(long)H_DIM * S_DIM * KD_DIM / 2];
__device__ uint32_t g_vhi [(long)H_DIM * S_DIM * E_DIM / 2];
__device__ uint32_t g_vlo [(long)H_DIM * S_DIM * E_DIM / 2];
__device__ uint32_t g_athi[(long)H_DIM * S_DIM * S_DIM / 2];
__device__ uint32_t g_atlo[(long)H_DIM * S_DIM * S_DIM / 2];
__device__ uint32_t g_hhi [(long)S_DIM * E_DIM / 2];
__device__ uint32_t g_hlo [(long)S_DIM * E_DIM / 2];
__device__ uint32_t g_ffhi[(long)S_DIM * FF_DIM / 2];
__device__ uint32_t g_fflo[(long)S_DIM * FF_DIM / 2];

// ===================== helpers ==============================================
__device__ __forceinline__ void split_pair(float f0, float f1,
                                           uint32_t &hi, uint32_t &lo)
{
    __nv_bfloat16 h0 = __float2bfloat16_rn(f0);
    __nv_bfloat16 h1 = __float2bfloat16_rn(f1);
    __nv_bfloat16 l0 = __float2bfloat16_rn(f0 - __bfloat162float(h0));
    __nv_bfloat16 l1 = __float2bfloat16_rn(f1 - __bfloat162float(h1));
    unsigned short u0 = __bfloat16_as_ushort(h0);
    unsigned short u1 = __bfloat16_as_ushort(h1);
    unsigned short w0 = __bfloat16_as_ushort(l0);
    unsigned short w1 = __bfloat16_as_ushort(l1);
    hi = (uint32_t)u0 | ((uint32_t)u1 << 16);
    lo = (uint32_t)w0 | ((uint32_t)w1 << 16);
}

// split fp32 X (pairs of linearly adjacent elements) -> hi/lo words (A-type)
__global__ void __launch_bounds__(256) split_rowpair(
    const float *in, uint32_t *hi, uint32_t *lo, long nwords)
{
    long stride = (long)gridDim.x * 256;
    long i;
    for (i = (long)blockIdx.x * 256 + threadIdx.x; i < nwords; i += stride) {
        float a = in[2 * i];
        float b = in[2 * i + 1];
        uint32_t h, l;
        split_pair(a, b, h, l);
        hi[i] = h;
        lo[i] = l;
    }
}

// split fp32 X[batch][K][N] pairing along K -> word[(b)(k/2)(n)] (B-type)
__global__ void __launch_bounds__(256) split_colpair(
    const float *in, uint32_t *hi, uint32_t *lo, int K, int N, long nwords)
{
    long stride = (long)gridDim.x * 256;
    long i;
    long k2n = (long)(K / 2) * N;
    for (i = (long)blockIdx.x * 256 + threadIdx.x; i < nwords; i += stride) {
        long b = i / k2n;
        long rem = i - b * k2n;
        long k2 = rem / N;
        long n = rem - k2 * N;
        const float *base = in + b * (long)K * N;
        float x0 = base[(2 * k2) * (long)N + n];
        float x1 = base[(2 * k2 + 1) * (long)N + n];
        uint32_t h, l;
        split_pair(x0, x1, h, l);
        hi[i] = h;
        lo[i] = l;
    }
}

// ===================== bf16-pair SIMT HMMA engine ===========================
#define PITCH 136

struct SmemTiles {
    uint32_t AsH[8][PITCH];
    uint32_t AsL[8][PITCH];
    uint32_t BsH[8][PITCH];
    uint32_t BsL[8][PITCH];
};

__device__ __forceinline__ void mma16816(float *c, const uint32_t *a,
                                         const uint32_t *b)
{
    asm volatile(
        "mma.sync.aligned.m16n8k16.row.col.f32.bf16.bf16.f32 "
        "{%0,%1,%2,%3},{%4,%5,%6,%7},{%8,%9},{%0,%1,%2,%3};\n"
        : "+f"(c[0]), "+f"(c[1]), "+f"(c[2]), "+f"(c[3])
        : "r"(a[0]), "r"(a[1]), "r"(a[2]), "r"(a[3]), "r"(b[0]), "r"(b[1]));
}

__device__ __forceinline__ void compute_stage(const SmemTiles *sm,
    float acc[4][4][4], int m0w, int n0w, int g, int t)
{
    uint32_t bh[4][2];
    uint32_t bl[4][2];
    int na, ma;
    #pragma unroll
    for (na = 0; na < 4; na++) {
        int c = n0w + na * 8 + g;
        bh[na][0] = sm->BsH[t][c];
        bh[na][1] = sm->BsH[t + 4][c];
        bl[na][0] = sm->BsL[t][c];
        bl[na][1] = sm->BsL[t + 4][c];
    }
    #pragma unroll
    for (ma = 0; ma < 4; ma++) {
        int r0 = m0w + ma * 16 + g;
        uint32_t ah[4];
        uint32_t al[4];
        ah[0] = sm->AsH[t][r0];
        ah[1] = sm->AsH[t][r0 + 8];
        ah[2] = sm->AsH[t + 4][r0];
        ah[3] = sm->AsH[t + 4][r0 + 8];
        al[0] = sm->AsL[t][r0];
        al[1] = sm->AsL[t][r0 + 8];
        al[2] = sm->AsL[t + 4][r0];
        al[3] = sm->AsL[t + 4][r0 + 8];
        #pragma unroll
        for (na = 0; na < 4; na++) {
            mma16816(acc[ma][na], ah, bh[na]);
            mma16816(acc[ma][na], ah, bl[na]);
            mma16816(acc[ma][na], al, bh[na]);
        }
    }
}

// stage pre-split A words (uint4 hi/lo) column-wise into smem rows k2b..+3
__device__ __forceinline__ void put_colstage(uint32_t (*Hi)[PITCH],
    uint32_t (*Lo)[PITCH], uint4 h4, uint4 l4, int k2b, int row)
{
    Hi[k2b + 0][row] = h4.x;
    Hi[k2b + 1][row] = h4.y;
    Hi[k2b + 2][row] = h4.z;
    Hi[k2b + 3][row] = h4.w;
    Lo[k2b + 0][row] = l4.x;
    Lo[k2b + 1][row] = l4.y;
    Lo[k2b + 2][row] = l4.z;
    Lo[k2b + 3][row] = l4.w;
}

__device__ __forceinline__ void put_rowstage(SmemTiles *sm,
    uint4 h4, uint4 l4, int k2, int nc)
{
    sm->BsH[k2][nc + 0] = h4.x;
    sm->BsH[k2][nc + 1] = h4.y;
    sm->BsH[k2][nc + 2] = h4.z;
    sm->BsH[k2][nc + 3] = h4.w;
    sm->BsL[k2][nc + 0] = l4.x;
    sm->BsL[k2][nc + 1] = l4.y;
    sm->BsL[k2][nc + 2] = l4.z;
    sm->BsL[k2][nc + 3] = l4.w;
}

// ---------------- C = A @ B from pre-split operands -------------------------
// A: A-type words [M][K/2] (+ z*sA2).  B: B-type words [K/2][N] (+ z*sB2).
// Outputs: optional fp32 C, optional paired-split (Chi/Clo, A-type).
__global__ void __launch_bounds__(256) bf_gemm(
    const uint32_t *Ahi, const uint32_t *Alo,
    const uint32_t *Bhi, const uint32_t *Blo,
    const float *bias, const float *resid,
    float *Cf, uint32_t *Chi, uint32_t *Clo,
    int K, int N,
    long sA2, long sB2, long sBias, long sCf, long sC2, int relu)
{
    __shared__ SmemTiles sm[2];

    long zo = (long)blockIdx.z;
    const uint32_t *AH = Ahi + zo * sA2;
    const uint32_t *AL = Alo + zo * sA2;
    const uint32_t *BH = Bhi + zo * sB2;
    const uint32_t *BL = Blo + zo * sB2;
    const float *bi = (bias != 0) ? (bias + zo * sBias) : (const float *)0;

    int tid = threadIdx.x;
    int lane = tid & 31;
    int warp = tid >> 5;
    int g = lane >> 2;
    int t = lane & 3;
    int m0w = (warp >> 2) * 64;
    int n0w = (warp & 3) * 32;
    long row0 = (long)blockIdx.y * 128;
    long col0 = (long)blockIdx.x * 128;

    int arow = tid >> 1;
    int aw4 = (tid & 1) * 4;   // word offset within the 8-word chunk
    int bkr = tid >> 5;
    int bnc = (tid & 31) * 4;

    int K2 = K / 2;

    float acc[4][4][4];
    int i0, i1, i2;
    #pragma unroll
    for (i0 = 0; i0 < 4; i0++)
        #pragma unroll
        for (i1 = 0; i1 < 4; i1++)
            #pragma unroll
            for (i2 = 0; i2 < 4; i2++)
                acc[i0][i1][i2] = 0.0f;

    const uint32_t *ahp = AH + (row0 + arow) * (long)K2 + aw4;
    const uint32_t *alp = AL + (row0 + arow) * (long)K2 + aw4;
    const uint32_t *bhp = BH + (long)bkr * N + col0 + bnc;
    const uint32_t *blp = BL + (long)bkr * N + col0 + bnc;

    uint4 pah = *(const uint4 *)(ahp);
    uint4 pal = *(const uint4 *)(alp);
    uint4 pbh = *(const uint4 *)(bhp);
    uint4 pbl = *(const uint4 *)(blp);

    put_colstage(sm[0].AsH, sm[0].AsL, pah, pal, aw4, arow);
    put_rowstage(&sm[0], pbh, pbl, bkr, bnc);
    __syncthreads();

    int nsteps = K / 16;
    int s;
    for (s = 0; s < nsteps; s++) {
        int more = (s + 1 < nsteps) ? 1 : 0;
        if (more) {
            long ko = (long)(s + 1) * 8;
            pah = *(const uint4 *)(ahp + ko);
            pal = *(const uint4 *)(alp + ko);
            pbh = *(const uint4 *)(bhp + ko * N);
            pbl = *(const uint4 *)(blp + ko * N);
        }
        compute_stage(&sm[s & 1], acc, m0w, n0w, g, t);
        if (more) {
            put_colstage(sm[(s + 1) & 1].AsH, sm[(s + 1) & 1].AsL,
                         pah, pal, aw4, arow);
            put_rowstage(&sm[(s + 1) & 1], pbh, pbl, bkr, bnc);
            __syncthreads();
        }
    }

    float *cf = (Cf != 0) ? (Cf + zo * sCf) : (float *)0;
    uint32_t *chi = (Chi != 0) ? (Chi + zo * sC2) : (uint32_t *)0;
    uint32_t *clo = (Clo != 0) ? (Clo + zo * sC2) : (uint32_t *)0;
    int N2 = N / 2;

    int ma, na;
    #pragma unroll
    for (ma = 0; ma < 4; ma++) {
        long r = row0 + m0w + ma * 16 + g;
        #pragma unroll
        for (na = 0; na < 4; na++) {
            long c = col0 + n0w + na * 8 + 2 * t;
            float b0 = 0.0f;
            float b1 = 0.0f;
            if (bi != 0) {
                b0 = bi[c];
                b1 = bi[c + 1];
            }
            float v0 = acc[ma][na][0] + b0;
            float v1 = acc[ma][na][1] + b1;
            float w0 = acc[ma][na][2] + b0;
            float w1 = acc[ma][na][3] + b1;
            if (resid != 0) {
                v0 += resid[r * N + c];
                v1 += resid[r * N + c + 1];
                w0 += resid[(r + 8) * N + c];
                w1 += resid[(r + 8) * N + c + 1];
            }
            if (relu != 0) {
                v0 = fmaxf(v0, 0.0f);
                v1 = fmaxf(v1, 0.0f);
                w0 = fmaxf(w0, 0.0f);
                w1 = fmaxf(w1, 0.0f);
            }
            if (cf != 0) {
                cf[r * N + c]           = v0;
                cf[r * N + c + 1]       = v1;
                cf[(r + 8) * N + c]     = w0;
                cf[(r + 8) * N + c + 1] = w1;
            }
            if (chi != 0) {
                uint32_t h0, l0, h1, l1;
                split_pair(v0, v1, h0, l0);
                split_pair(w0, w1, h1, l1);
                chi[r * N2 + c / 2]       = h0;
                clo[r * N2 + c / 2]       = l0;
                chi[(r + 8) * N2 + c / 2] = h1;
                clo[(r + 8) * N2 + c / 2] = l1;
            }
        }
    }
}

// ---------------- scores = (Q @ K^T)/sqrt(KD), causal block skip ------------
// Q, K pre-split A-type words [S][KD/2] per head.
__global__ void __launch_bounds__(256) bf_qkt(
    const uint32_t *Qhi, const uint32_t *Qlo,
    const uint32_t *Khi, const uint32_t *Klo,
    float *SCg, float scale)
{
    __shared__ SmemTiles sm[2];

    if (blockIdx.x > blockIdx.y) return;
    long zo = (long)blockIdx.z * S_DIM * (KD_DIM / 2);
    const uint32_t *QH = Qhi + zo;
    const uint32_t *QL = Qlo + zo;
    const uint32_t *KH = Khi + zo;
    const uint32_t *KL = Klo + zo;
    float *C = SCg + (long)blockIdx.z * S_DIM * (long)S_DIM;

    int tid = threadIdx.x;
    int lane = tid & 31;
    int warp = tid >> 5;
    int g = lane >> 2;
    int t = lane & 3;
    int m0w = (warp >> 2) * 64;
    int n0w = (warp & 3) * 32;
    long row0 = (long)blockIdx.y * 128;
    long col0 = (long)blockIdx.x * 128;

    int arow = tid >> 1;
    int aw4 = (tid & 1) * 4;
    int K2 = KD_DIM / 2;

    float acc[4][4][4];
    int i0, i1, i2;
    #pragma unroll
    for (i0 = 0; i0 < 4; i0++)
        #pragma unroll
        for (i1 = 0; i1 < 4; i1++)
            #pragma unroll
            for (i2 = 0; i2 < 4; i2++)
                acc[i0][i1][i2] = 0.0f;

    const uint32_t *qhp = QH + (row0 + arow) * (long)K2 + aw4;
    const uint32_t *qlp = QL + (row0 + arow) * (long)K2 + aw4;
    const uint32_t *khp = KH + (col0 + arow) * (long)K2 + aw4;
    const uint32_t *klp = KL + (col0 + arow) * (long)K2 + aw4;

    uint4 pah = *(const uint4 *)(qhp);
    uint4 pal = *(const uint4 *)(qlp);
    uint4 pbh = *(const uint4 *)(khp);
    uint4 pbl = *(const uint4 *)(klp);

    put_colstage(sm[0].AsH, sm[0].AsL, pah, pal, aw4, arow);
    put_colstage(sm[0].BsH, sm[0].BsL, pbh, pbl, aw4, arow);
    __syncthreads();

    int nsteps = KD_DIM / 16;
    int s;
    for (s = 0; s < nsteps; s++) {
        int more = (s + 1 < nsteps) ? 1 : 0;
        if (more) {
            long ko = (long)(s + 1) * 8;
            pah = *(const uint4 *)(qhp + ko);
            pal = *(const uint4 *)(qlp + ko);
            pbh = *(const uint4 *)(khp + ko);
            pbl = *(const uint4 *)(klp + ko);
        }
        compute_stage(&sm[s & 1], acc, m0w, n0w, g, t);
        if (more) {
            put_colstage(sm[(s + 1) & 1].AsH, sm[(s + 1) & 1].AsL,
                         pah, pal, aw4, arow);
            put_colstage(sm[(s + 1) & 1].BsH, sm[(s + 1) & 1].BsL,
                         pbh, pbl, aw4, arow);
            __syncthreads();
        }
    }

    int ma, na;
    #pragma unroll
    for (ma = 0; ma < 4; ma++) {
        long r = row0 + m0w + ma * 16 + g;
        #pragma unroll
        for (na = 0; na < 4; na++) {
            long c = col0 + n0w + na * 8 + 2 * t;
            C[r * S_DIM + c]           = acc[ma][na][0] * scale;
            C[r * S_DIM + c + 1]       = acc[ma][na][1] * scale;
            C[(r + 8) * S_DIM + c]     = acc[ma][na][2] * scale;
            C[(r + 8) * S_DIM + c + 1] = acc[ma][na][3] * scale;
        }
    }
}

// ---------------- partial[z] = sum_{h in group z} attn[h] @ V[h] ------------
// attn split A-type [H][S][S/2]; V split B-type [H][S/2][E]; bounded k.
__global__ void __launch_bounds__(256) bf_attn_av(
    const uint32_t *Athi, const uint32_t *Atlo,
    const uint32_t *Vhi, const uint32_t *Vlo,
    float *Pg)
{
    __shared__ SmemTiles sm[2];

    int tid = threadIdx.x;
    int lane = tid & 31;
    int warp = tid >> 5;
    int g = lane >> 2;
    int t = lane & 3;
    int m0w = (warp >> 2) * 64;
    int n0w = (warp & 3) * 32;
    long row0 = (long)blockIdx.y * 128;
    long col0 = (long)blockIdx.x * 128;

    int arow = tid >> 1;
    int aw4 = (tid & 1) * 4;
    int bkr = tid >> 5;
    int bnc = (tid & 31) * 4;

    int nk = ((int)blockIdx.y + 1) * 8;  // k16 steps per head
    int total = 4 * nk;                  // 4 heads per group
    int h0 = (int)blockIdx.z * 4;
    long S2 = S_DIM / 2;

    float acc[4][4][4];
    int i0, i1, i2;
    #pragma unroll
    for (i0 = 0; i0 < 4; i0++)
        #pragma unroll
        for (i1 = 0; i1 < 4; i1++)
            #pragma unroll
            for (i2 = 0; i2 < 4; i2++)
                acc[i0][i1][i2] = 0.0f;

    uint4 pah, pal, pbh, pbl;
    {
        long ab = ((long)h0 * S_DIM + row0 + arow) * S2 + aw4;
        long bb = (long)h0 * S2 * E_DIM + (long)bkr * E_DIM + col0 + bnc;
        pah = *(const uint4 *)(Athi + ab);
        pal = *(const uint4 *)(Atlo + ab);
        pbh = *(const uint4 *)(Vhi + bb);
        pbl = *(const uint4 *)(Vlo + bb);
    }
    put_colstage(sm[0].AsH, sm[0].AsL, pah, pal, aw4, arow);
    put_rowstage(&sm[0], pbh, pbl, bkr, bnc);
    __syncthreads();

    int h = h0;
    int ks = 0;
    int it;
    for (it = 0; it < total; it++) {
        int more = (it + 1 < total) ? 1 : 0;
        int h2 = h;
        int k2 = ks + 1;
        if (k2 == nk) {
            k2 = 0;
            h2 = h2 + 1;
        }
        if (more) {
            long ab = ((long)h2 * S_DIM + row0 + arow) * S2 + k2 * 8 + aw4;
            long bb = (long)h2 * S2 * E_DIM
                    + (long)(k2 * 8 + bkr) * E_DIM + col0 + bnc;
            pah = *(const uint4 *)(Athi + ab);
            pal = *(const uint4 *)(Atlo + ab);
            pbh = *(const uint4 *)(Vhi + bb);
            pbl = *(const uint4 *)(Vlo + bb);
        }
        compute_stage(&sm[it & 1], acc, m0w, n0w, g, t);
        if (more) {
            put_colstage(sm[(it + 1) & 1].AsH, sm[(it + 1) & 1].AsL,
                         pah, pal, aw4, arow);
            put_rowstage(&sm[(it + 1) & 1], pbh, pbl, bkr, bnc);
            __syncthreads();
        }
        h = h2;
        ks = k2;
    }

    float *P = Pg + (long)blockIdx.z * S_DIM * E_DIM;
    int ma, na;
    #pragma unroll
    for (ma = 0; ma < 4; ma++) {
        long r = row0 + m0w + ma * 16 + g;
        #pragma unroll
        for (na = 0; na < 4; na++) {
            long c = col0 + n0w + na * 8 + 2 * t;
            P[r * E_DIM + c]           = acc[ma][na][0];
            P[r * E_DIM + c + 1]       = acc[ma][na][1];
            P[(r + 8) * E_DIM + c]     = acc[ma][na][2];
            P[(r + 8) * E_DIM + c + 1] = acc[ma][na][3];
        }
    }
}

// py = x + p0 + p1 + p2 + p3 (fixed order, deterministic)
__global__ void __launch_bounds__(256) reduce4(
    const float *x, const float *p, float *py)
{
    long stride = (long)gridDim.x * 256;
    long i;
    for (i = (long)blockIdx.x * 256 + threadIdx.x; i < NTOT; i += stride) {
        float v = x[i];
        v += p[i];
        v += p[NTOT + i];
        v += p[2 * NTOT + i];
        v += p[3 * NTOT + i];
        py[i] = v;
    }
}

// ---------------- causal row softmax -> split attn (hi/lo pairs) ------------
__global__ void __launch_bounds__(256) softmax_causal(
    const float *sc, uint32_t *athi, uint32_t *atlo)
{
    __shared__ float buf[S_DIM];
    __shared__ float red[256];

    int s = blockIdx.x;
    int h = blockIdx.y;
    const float *row = sc + ((long)h * S_DIM + s) * (long)S_DIM;
    long out2 = ((long)h * S_DIM + s) * (long)(S_DIM / 2);
    int tid = threadIdx.x;
    int len = s + 1;
    int i;
    int st;

    float lmax = -INFINITY;
    for (i = tid; i < len; i += 256) {
        float v = row[i];
        buf[i] = v;
        lmax = fmaxf(lmax, v);
    }
    red[tid] = lmax;
    __syncthreads();
    for (st = 128; st > 0; st >>= 1) {
        if (tid < st) red[tid] = fmaxf(red[tid], red[tid + st]);
        __syncthreads();
    }
    float m = red[0];
    __syncthreads();

    float lsum = 0.0f;
    for (i = tid; i < len; i += 256) {
        float e = __expf(buf[i] - m);
        buf[i] = e;
        lsum += e;
    }
    red[tid] = lsum;
    __syncthreads();
    for (st = 128; st > 0; st >>= 1) {
        if (tid < st) red[tid] = red[tid] + red[tid + st];
        __syncthreads();
    }
    float inv = 1.0f / red[0];
    for (i = tid; i < S_DIM / 2; i += 256) {
        int i0 = 2 * i;
        int i1 = 2 * i + 1;
        float a = (i0 < len) ? buf[i0] * inv : 0.0f;
        float b = (i1 < len) ? buf[i1] * inv : 0.0f;
        uint32_t hh, ll;
        split_pair(a, b, hh, ll);
        athi[out2 + i] = hh;
        atlo[out2 + i] = ll;
    }
}

// ---------------- global LayerNorm ------------------------------------------
__global__ void __launch_bounds__(256) ln_reduce(const float *y, double *part)
{
    __shared__ double sd[256];
    __shared__ double sq[256];

    double s = 0.0;
    double ss = 0.0;
    long stride = (long)gridDim.x * 256;
    long i;
    int st;
    for (i = (long)blockIdx.x * 256 + threadIdx.x; i < NTOT; i += stride) {
        double v = (double)y[i];
        s += v;
        ss += v * v;
    }
    sd[threadIdx.x] = s;
    sq[threadIdx.x] = ss;
    __syncthreads();
    for (st = 128; st > 0; st >>= 1) {
        if (threadIdx.x < st) {
            sd[threadIdx.x] = sd[threadIdx.x] + sd[threadIdx.x + st];
            sq[threadIdx.x] = sq[threadIdx.x] + sq[threadIdx.x + st];
        }
        __syncthreads();
    }
    if (threadIdx.x == 0) {
        part[blockIdx.x] = sd[0];
        part[1024 + blockIdx.x] = sq[0];
    }
}

__global__ void __launch_bounds__(256) ln_finalize(const double *part, float *stats)
{
    __shared__ double sd[256];
    __shared__ double sq[256];

    double s = 0.0;
    double ss = 0.0;
    int i;
    int st;
    for (i = threadIdx.x; i < 1024; i += 256) {
        s += part[i];
        ss += part[1024 + i];
    }
    sd[threadIdx.x] = s;
    sq[threadIdx.x] = ss;
    __syncthreads();
    for (st = 128; st > 0; st >>= 1) {
        if (threadIdx.x < st) {
            sd[threadIdx.x] = sd[threadIdx.x] + sd[threadIdx.x + st];
            sq[threadIdx.x] = sq[threadIdx.x] + sq[threadIdx.x + st];
        }
        __syncthreads();
    }
    if (threadIdx.x == 0) {
        double mean = sd[0] / (double)NTOT;
        double var = sq[0] / (double)NTOT - mean * mean;
        stats[0] = (float)mean;
        stats[1] = (float)(1.0 / sqrt(var + (double)EPS));
    }
}

// LN apply with optional fp32 out and optional split out (pairs)
__global__ void __launch_bounds__(256) ln_apply(
    const float *y, const float *g, const float *b,
    const float *st, float *of32, uint32_t *ohi, uint32_t *olo)
{
    float m = st[0];
    float is = st[1];
    long stride = (long)gridDim.x * 256;
    long i;
    for (i = (long)blockIdx.x * 256 + threadIdx.x; i < NTOT / 2; i += stride) {
        long i0 = 2 * i;
        long i1 = 2 * i + 1;
        float v0 = (y[i0] - m) * is * g[i0] + b[i0];
        float v1 = (y[i1] - m) * is * g[i1] + b[i1];
        if (of32 != 0) {
            of32[i0] = v0;
            of32[i1] = v1;
        }
        if (ohi != 0) {
            uint32_t hh, ll;
            split_pair(v0, v1, hh, ll);
            ohi[i] = hh;
            olo[i] = ll;
        }
    }
}

// ---------------- host orchestration ----------------------------------------
extern "C" void kernel_launch(void* const* d_in, const int* in_sizes, int n_in,
                              void* d_out, int out_size)
{
    const float *x  = (const float *)d_in[0];
    const float *Wq = (const float *)d_in[1];
    const float *bq = (const float *)d_in[2];
    const float *Wk = (const float *)d_in[3];
    const float *bk = (const float *)d_in[4];
    const float *Wv = (const float *)d_in[5];
    const float *bv = (const float *)d_in[6];
    const float *lg = (const float *)d_in[7];
    const float *lb = (const float *)d_in[8];
    const float *W1 = (const float *)d_in[9];
    const float *b1 = (const float *)d_in[10];
    const float *W2 = (const float *)d_in[11];
    const float *b2 = (const float *)d_in[12];
    float *out = (float *)d_out;

    void *pv_[32];
    cudaGetSymbolAddress(&pv_[0],  g_v);
    cudaGetSymbolAddress(&pv_[1],  g_sc);
    cudaGetSymbolAddress(&pv_[2],  g_y);
    cudaGetSymbolAddress(&pv_[3],  g_h);
    cudaGetSymbolAddress(&pv_[4],  g_pt);
    cudaGetSymbolAddress(&pv_[5],  g_part);
    cudaGetSymbolAddress(&pv_[6],  g_stats);
    cudaGetSymbolAddress(&pv_[7],  g_xhi);
    cudaGetSymbolAddress(&pv_[8],  g_xlo);
    cudaGetSymbolAddress(&pv_[9],  g_wqhi);
    cudaGetSymbolAddress(&pv_[10], g_wqlo);
    cudaGetSymbolAddress(&pv_[11], g_wkhi);
    cudaGetSymbolAddress(&pv_[12], g_wklo);
    cudaGetSymbolAddress(&pv_[13], g_wvhi);
    cudaGetSymbolAddress(&pv_[14], g_wvlo);
    cudaGetSymbolAddress(&pv_[15], g_w1hi);
    cudaGetSymbolAddress(&pv_[16], g_w1lo);
    cudaGetSymbolAddress(&pv_[17], g_w2hi);
    cudaGetSymbolAddress(&pv_[18], g_w2lo);
    cudaGetSymbolAddress(&pv_[19], g_qhi);
    cudaGetSymbolAddress(&pv_[20], g_qlo);
    cudaGetSymbolAddress(&pv_[21], g_khi);
    cudaGetSymbolAddress(&pv_[22], g_klo);
    cudaGetSymbolAddress(&pv_[23], g_vhi);
    cudaGetSymbolAddress(&pv_[24], g_vlo);
    cudaGetSymbolAddress(&pv_[25], g_athi);
    cudaGetSymbolAddress(&pv_[26], g_atlo);
    cudaGetSymbolAddress(&pv_[27], g_hhi);
    cudaGetSymbolAddress(&pv_[28], g_hlo);
    cudaGetSymbolAddress(&pv_[29], g_ffhi);
    cudaGetSymbolAddress(&pv_[30], g_fflo);

    float *pvv   = (float *)pv_[0];
    float *psc   = (float *)pv_[1];
    float *py    = (float *)pv_[2];
    float *ph    = (float *)pv_[3];
    float *ppt   = (float *)pv_[4];
    double *ppart = (double *)pv_[5];
    float *pstats = (float *)pv_[6];
    uint32_t *xhi = (uint32_t *)pv_[7],  *xlo = (uint32_t *)pv_[8];
    uint32_t *wqh = (uint32_t *)pv_[9],  *wql = (uint32_t *)pv_[10];
    uint32_t *wkh = (uint32_t *)pv_[11], *wkl = (uint32_t *)pv_[12];
    uint32_t *wvh = (uint32_t *)pv_[13], *wvl = (uint32_t *)pv_[14];
    uint32_t *w1h = (uint32_t *)pv_[15], *w1l = (uint32_t *)pv_[16];
    uint32_t *w2h = (uint32_t *)pv_[17], *w2l = (uint32_t *)pv_[18];
    uint32_t *qh  = (uint32_t *)pv_[19], *ql  = (uint32_t *)pv_[20];
    uint32_t *kh  = (uint32_t *)pv_[21], *kl  = (uint32_t *)pv_[22];
    uint32_t *vh  = (uint32_t *)pv_[23], *vl  = (uint32_t *)pv_[24];
    uint32_t *ath = (uint32_t *)pv_[25], *atl = (uint32_t *)pv_[26];
    uint32_t *hh  = (uint32_t *)pv_[27], *hl  = (uint32_t *)pv_[28];
    uint32_t *ffh = (uint32_t *)pv_[29], *ffl = (uint32_t *)pv_[30];

    dim3 blk(256, 1, 1);
    float scale = 1.0f / sqrtf((float)KD_DIM);

    // -------- operand splits --------
    split_rowpair<<<2048, blk>>>(x, xhi, xlo, NTOT / 2);
    split_colpair<<<2048, blk>>>(Wq, wqh, wql, E_DIM, KD_DIM,
                                 (long)H_DIM * E_DIM * KD_DIM / 2);
    split_colpair<<<2048, blk>>>(Wk, wkh, wkl, E_DIM, KD_DIM,
                                 (long)H_DIM * E_DIM * KD_DIM / 2);
    split_colpair<<<4096, blk>>>(Wv, wvh, wvl, E_DIM, E_DIM,
                                 (long)H_DIM * E_DIM * E_DIM / 2);
    split_colpair<<<2048, blk>>>(W1, w1h, w1l, E_DIM, FF_DIM,
                                 (long)E_DIM * FF_DIM / 2);
    split_colpair<<<2048, blk>>>(W2, w2h, w2l, FF_DIM, E_DIM,
                                 (long)FF_DIM * E_DIM / 2);

    // -------- Q/K projections (split outputs) --------
    {
        dim3 gq(1, S_DIM / 128, H_DIM);
        bf_gemm<<<gq, blk>>>(xhi, xlo, wqh, wql, bq, (const float *)0,
            (float *)0, qh, ql, E_DIM, KD_DIM,
            0L, (long)(E_DIM / 2) * KD_DIM, (long)KD_DIM,
            0L, (long)S_DIM * (KD_DIM / 2), 0);
        bf_gemm<<<gq, blk>>>(xhi, xlo, wkh, wkl, bk, (const float *)0,
            (float *)0, kh, kl, E_DIM, KD_DIM,
            0L, (long)(E_DIM / 2) * KD_DIM, (long)KD_DIM,
            0L, (long)S_DIM * (KD_DIM / 2), 0);
    }
    // -------- V projection (fp32 out), then B-type split --------
    {
        dim3 gv(E_DIM / 128, S_DIM / 128, H_DIM);
        bf_gemm<<<gv, blk>>>(xhi, xlo, wvh, wvl, bv, (const float *)0,
            pvv, (uint32_t *)0, (uint32_t *)0, E_DIM, E_DIM,
            0L, (long)(E_DIM / 2) * E_DIM, (long)E_DIM,
            (long)S_DIM * E_DIM, 0L, 0);
        split_colpair<<<4096, blk>>>(pvv, vh, vl, S_DIM, E_DIM,
                                     (long)H_DIM * S_DIM * E_DIM / 2);
    }

    // -------- scores + causal softmax (fused attn split) --------
    {
        dim3 gs(S_DIM / 128, S_DIM / 128, H_DIM);
        bf_qkt<<<gs, blk>>>(qh, ql, kh, kl, psc, scale);
    }
    {
        dim3 gsm(S_DIM, H_DIM, 1);
        softmax_causal<<<gsm, blk>>>(psc, ath, atl);
    }

    // -------- attn @ V: 4 balanced head-groups + deterministic reduce -------
    {
        dim3 ga(E_DIM / 128, S_DIM / 128, 4);
        bf_attn_av<<<ga, blk>>>(ath, atl, vh, vl, ppt);
        reduce4<<<2048, blk>>>(x, ppt, py);
    }

    // -------- LN1 (fp32 h for FFN2 resid + split h for FFN1) --------
    ln_reduce<<<1024, blk>>>(py, ppart);
    ln_finalize<<<1, blk>>>(ppart, pstats);
    ln_apply<<<2048, blk>>>(py, lg, lb, pstats, ph, hh, hl);

    // -------- FFN --------
    {
        dim3 g1(FF_DIM / 128, S_DIM / 128, 1);
        bf_gemm<<<g1, blk>>>(hh, hl, w1h, w1l, b1, (const float *)0,
            (float *)0, ffh, ffl, E_DIM, FF_DIM,
            0L, 0L, 0L, 0L, 0L, 1);
        dim3 g2(E_DIM / 128, S_DIM / 128, 1);
        bf_gemm<<<g2, blk>>>(ffh, ffl, w2h, w2l, b2, ph,
            py, (uint32_t *)0, (uint32_t *)0, FF_DIM, E_DIM,
            0L, 0L, 0L, (long)S_DIM * E_DIM, 0L, 0);
    }

    // -------- LN2 -> output --------
    ln_reduce<<<1024, blk>>>(py, ppart);
    ln_finalize<<<1, blk>>>(ppart, pstats);
    ln_apply<<<2048, blk>>>(py, lg, lb, pstats, out, (uint32_t *)0,
                            (uint32_t *)0);
}